// round 11
// baseline (speedup 1.0000x reference)
#include <cuda_runtime.h>
#include <cstdint>
#include <cstddef>

// Butterfly transform: B=8192 rows, N=4096, 12 stages, increasing stride.
// R11 = R10 (best, 84.5us) + wave-balance attack:
//  - tile grows 12 -> 14 rows (7 float2 pairs, 224KB smem, fits 227KB max):
//    586 tiles / 148 CTAs = 3.96 -> max 4 tiles/CTA (was 5 of 4.61 -> 8.4%
//    idle tail). Twiddle reg-cache now amortized over 7 pairs (-14% L2).
//  - persistent 148-CTA grid + L2 prefetch of the CTA's next tile (kept).
//  - phase-scoped 48-reg twiddle caches (R8 lesson), float2 pair packing,
//    4 register phases x 3 stages, 3 smem exchanges, proven swizzle.

namespace {
constexpr int kN       = 4096;
constexpr int kBatch   = 8192;
constexpr int kThreads = 512;
constexpr int kRows    = 14;
constexpr int kPairs   = kRows / 2;                         // 7
constexpr int kTiles   = 586;    // 585 full (14 rows) + 1 tail (2 rows)
constexpr int kGrid    = 148;                               // persistent
constexpr int kSmem    = kPairs * kN * (int)sizeof(float2); // 229376 B
constexpr int kTileChunks = kRows * kN * 4 / 128;           // 1792 x 128B
}

// float2-granule swizzle; conflict-free for i = base + s*m, s in {1,8,64,512}
// (verified per half-warp for all four phase ownerships).
__device__ __forceinline__ int swz(int i) {
    return (i & ~15) | ((i & 15) ^ ((i >> 4) & 7) ^ ((i >> 3) & 8));
}

__device__ __forceinline__ void prefetch_l2(const void* p) {
    asm volatile("prefetch.global.L2 [%0];" :: "l"(p));
}

// One 2x2 butterfly applied to two rows packed in float2 lanes.
__device__ __forceinline__ void bfly(float2& x0, float2& x1, const float4 tm) {
    float2 y0, y1;
    y0.x = __fmaf_rn(tm.y, x1.x, tm.x * x0.x);
    y0.y = __fmaf_rn(tm.y, x1.y, tm.x * x0.y);
    y1.x = __fmaf_rn(tm.w, x1.x, tm.z * x0.x);
    y1.y = __fmaf_rn(tm.w, x1.y, tm.z * x0.y);
    x0 = y0;
    x1 = y1;
}

// Three in-register substages over 8 owned elements (local strides 1,2,4).
__device__ __forceinline__ void substages(float2 v[8], const float4 twr[3][4]) {
    bfly(v[0], v[1], twr[0][0]); bfly(v[2], v[3], twr[0][1]);
    bfly(v[4], v[5], twr[0][2]); bfly(v[6], v[7], twr[0][3]);
    bfly(v[0], v[2], twr[1][0]); bfly(v[1], v[3], twr[1][1]);
    bfly(v[4], v[6], twr[1][2]); bfly(v[5], v[7], twr[1][3]);
    bfly(v[0], v[4], twr[2][0]); bfly(v[1], v[5], twr[2][1]);
    bfly(v[2], v[6], twr[2][2]); bfly(v[3], v[7], twr[2][3]);
}

template <int NPAIRS>
__device__ __forceinline__ void bf_body(const float* __restrict__ x,
                                        const float* __restrict__ tw,
                                        float* __restrict__ out,
                                        int row0, int nrow0, float2* buf) {
    const int t = threadIdx.x;
    const float4* tw4 = reinterpret_cast<const float4*>(tw);

    // ---------------- Phase 0: stages 0..2 (strides 1,2,4) ----------------
    {
        float4 twr[3][4];
        #pragma unroll
        for (int u = 0; u < 3; ++u)
            #pragma unroll
            for (int pm = 0; pm < 4; ++pm)
                twr[u][pm] = tw4[u * 2048 + 4 * t + pm];
        int off[8];
        #pragma unroll
        for (int m = 0; m < 8; ++m) off[m] = swz(8 * t + m);

        #pragma unroll
        for (int p = 0; p < NPAIRS; ++p) {
            const float4* xa =
                reinterpret_cast<const float4*>(x + (size_t)(row0 + 2 * p) * kN);
            const float4* xb =
                reinterpret_cast<const float4*>(x + (size_t)(row0 + 2 * p + 1) * kN);
            const float4 a0 = xa[2 * t], a1 = xa[2 * t + 1];
            const float4 b0 = xb[2 * t], b1 = xb[2 * t + 1];
            float2 v[8];
            v[0] = make_float2(a0.x, b0.x); v[1] = make_float2(a0.y, b0.y);
            v[2] = make_float2(a0.z, b0.z); v[3] = make_float2(a0.w, b0.w);
            v[4] = make_float2(a1.x, b1.x); v[5] = make_float2(a1.y, b1.y);
            v[6] = make_float2(a1.z, b1.z); v[7] = make_float2(a1.w, b1.w);

            substages(v, twr);

            float2* B = buf + p * kN;
            #pragma unroll
            for (int m = 0; m < 8; ++m) B[off[m]] = v[m];
        }
    }
    __syncthreads();

    // ------------- Phases 1,2: stages 3..8 (strides 8..256), smem ---------
    #pragma unroll
    for (int ph = 1; ph <= 2; ++ph) {
        const int ls = 3 * ph;          // 3 or 6
        const int s  = 1 << ls;         // 8 or 64
        const int b  = t >> ls;
        const int c  = t & (s - 1);

        float4 twr[3][4];
        #pragma unroll
        for (int u = 0; u < 3; ++u)
            #pragma unroll
            for (int pm = 0; pm < 4; ++pm)
                twr[u][pm] = tw4[(3 * ph + u) * 2048 + s * (4 * b + pm) + c];
        int off[8];
        #pragma unroll
        for (int m = 0; m < 8; ++m) off[m] = swz(b * 8 * s + c + s * m);

        // Prefetch the NEXT tile's 224KB into L2 under phases 1-3 compute.
        if (ph == 1 && nrow0 >= 0) {
            const char* nb = reinterpret_cast<const char*>(x + (size_t)nrow0 * kN);
            #pragma unroll
            for (int k = 0; k < 4; ++k) {
                const int idx = t + 512 * k;
                if (idx < kTileChunks)
                    prefetch_l2(nb + (size_t)idx * 128);
            }
        }

        #pragma unroll
        for (int p = 0; p < NPAIRS; ++p) {
            float2* B = buf + p * kN;
            float2 v[8];
            #pragma unroll
            for (int m = 0; m < 8; ++m) v[m] = B[off[m]];

            substages(v, twr);

            #pragma unroll
            for (int m = 0; m < 8; ++m) B[off[m]] = v[m];
        }
        __syncthreads();
    }

    // ------------- Phase 3: stages 9..11 (strides 512..2048) -> out -------
    {
        const int s = 512;  // b = 0, c = t
        float4 twr[3][4];
        #pragma unroll
        for (int u = 0; u < 3; ++u)
            #pragma unroll
            for (int pm = 0; pm < 4; ++pm)
                twr[u][pm] = tw4[(9 + u) * 2048 + s * pm + t];
        int off[8];
        #pragma unroll
        for (int m = 0; m < 8; ++m) off[m] = swz(t + s * m);

        #pragma unroll
        for (int p = 0; p < NPAIRS; ++p) {
            float2* B = buf + p * kN;
            float2 v[8];
            #pragma unroll
            for (int m = 0; m < 8; ++m) v[m] = B[off[m]];

            substages(v, twr);

            float* oa = out + (size_t)(row0 + 2 * p) * kN;
            float* ob = oa + kN;
            #pragma unroll
            for (int m = 0; m < 8; ++m) {
                oa[t + s * m] = v[m].x;   // warp-contiguous 4B stores
                ob[t + s * m] = v[m].y;
            }
        }
    }
    __syncthreads();   // smem slots reused by next tile's phase 0
}

__global__ void __launch_bounds__(kThreads, 1)
butterfly_kernel(const float* __restrict__ x,
                 const float* __restrict__ tw,
                 float* __restrict__ out) {
    extern __shared__ float2 buf[];

    for (int tile = blockIdx.x; tile < kTiles; tile += kGrid) {
        const int row0  = tile * kRows;
        const int nt    = tile + kGrid;
        const int nrow0 = (nt < kTiles) ? nt * kRows : -1;

        if (tile != kTiles - 1) {
            bf_body<7>(x, tw, out, row0, nrow0, buf);   // 14-row tiles
        } else {
            bf_body<1>(x, tw, out, row0, nrow0, buf);   // tail rows 8190..8191
        }
    }
}

extern "C" void kernel_launch(void* const* d_in, const int* in_sizes, int n_in,
                              void* d_out, int out_size) {
    const float* x  = (const float*)d_in[0];   // (8192, 4096) fp32
    const float* tw = (const float*)d_in[1];   // (1,1,12,2048,2,2) fp32
    float* out      = (float*)d_out;           // (8192, 4096) fp32

    cudaFuncSetAttribute(butterfly_kernel,
                         cudaFuncAttributeMaxDynamicSharedMemorySize, kSmem);
    butterfly_kernel<<<kGrid, kThreads, kSmem>>>(x, tw, out);
}

// round 12
// speedup vs baseline: 1.1102x; 1.1102x over previous
#include <cuda_runtime.h>
#include <cstdint>
#include <cstddef>

// Butterfly transform: B=8192 rows, N=4096, 12 stages, increasing stride.
// R12 = R10 (best, 84.5us: quad packing, 192KB smem, persistent 148 CTAs,
// L2 prefetch, phase-scoped twiddle caches) + balanced mixed tiling:
//   568 tiles of 12 rows + 172 tiles of 8 rows = 740 tiles = 148 x 5
//   -> every CTA runs exactly 5 tiles; critical CTA = 56 rows of work
//      (was 60 with 91 CTAs x 5 twelve-row tiles): ~6.7% wall reduction.
// Tile shape/smem (192KB) unchanged from R10 — R11 showed bigger smem tiles
// regress (L1D carveout). The 8-row body is R10's existing bf_body<2>.

namespace {
constexpr int kN       = 4096;
constexpr int kBatch   = 8192;
constexpr int kThreads = 512;
constexpr int kTiles12 = 568;                               // 12-row tiles
constexpr int kTiles   = 740;                               // = 148 * 5
constexpr int kGrid    = 148;                               // persistent
constexpr int kSmem    = 3 * kN * (int)sizeof(float4);      // 196608 B
}

// float4-granule swizzle: XOR low-3 index bits with bits 3..5.
__device__ __forceinline__ int swz(int i) { return i ^ ((i >> 3) & 7); }

__device__ __forceinline__ void prefetch_l2(const void* p) {
    asm volatile("prefetch.global.L2 [%0];" :: "l"(p));
}

// Row offset and row count for tile index i.
__device__ __forceinline__ int tile_row0(int i) {
    return (i < kTiles12) ? 12 * i : 12 * kTiles12 + 8 * (i - kTiles12);
}
__device__ __forceinline__ int tile_rows(int i) {
    return (i < kTiles12) ? 12 : 8;
}

// One 2x2 butterfly applied to four rows packed in float4 lanes.
__device__ __forceinline__ void bfly(float4& x0, float4& x1, const float4 tm) {
    float4 y0, y1;
    y0.x = __fmaf_rn(tm.y, x1.x, tm.x * x0.x);
    y0.y = __fmaf_rn(tm.y, x1.y, tm.x * x0.y);
    y0.z = __fmaf_rn(tm.y, x1.z, tm.x * x0.z);
    y0.w = __fmaf_rn(tm.y, x1.w, tm.x * x0.w);
    y1.x = __fmaf_rn(tm.w, x1.x, tm.z * x0.x);
    y1.y = __fmaf_rn(tm.w, x1.y, tm.z * x0.y);
    y1.z = __fmaf_rn(tm.w, x1.z, tm.z * x0.z);
    y1.w = __fmaf_rn(tm.w, x1.w, tm.z * x0.w);
    x0 = y0;
    x1 = y1;
}

// Three in-register substages over 8 owned elements (local strides 1,2,4).
__device__ __forceinline__ void substages(float4 v[8], const float4 twr[3][4]) {
    bfly(v[0], v[1], twr[0][0]); bfly(v[2], v[3], twr[0][1]);
    bfly(v[4], v[5], twr[0][2]); bfly(v[6], v[7], twr[0][3]);
    bfly(v[0], v[2], twr[1][0]); bfly(v[1], v[3], twr[1][1]);
    bfly(v[4], v[6], twr[1][2]); bfly(v[5], v[7], twr[1][3]);
    bfly(v[0], v[4], twr[2][0]); bfly(v[1], v[5], twr[2][1]);
    bfly(v[2], v[6], twr[2][2]); bfly(v[3], v[7], twr[2][3]);
}

template <int NQ>
__device__ __forceinline__ void bf_body(const float* __restrict__ x,
                                        const float* __restrict__ tw,
                                        float* __restrict__ out,
                                        int row0, int nrow0, int nchunks,
                                        float4* buf) {
    const int t = threadIdx.x;
    const float4* tw4 = reinterpret_cast<const float4*>(tw);

    // ---------------- Phase 0: stages 0..2 (strides 1,2,4) ----------------
    {
        float4 twr[3][4];
        #pragma unroll
        for (int u = 0; u < 3; ++u)
            #pragma unroll
            for (int pm = 0; pm < 4; ++pm)
                twr[u][pm] = tw4[u * 2048 + 4 * t + pm];
        int off[8];
        #pragma unroll
        for (int m = 0; m < 8; ++m) off[m] = swz(8 * t + m);

        #pragma unroll
        for (int q = 0; q < NQ; ++q) {
            // Load elements 8t..8t+7 of rows 4q..4q+3 (2 LDG.128 per row).
            float4 r[4][2];
            #pragma unroll
            for (int j = 0; j < 4; ++j) {
                const float4* xr = reinterpret_cast<const float4*>(
                    x + (size_t)(row0 + 4 * q + j) * kN);
                r[j][0] = __ldg(xr + 2 * t);
                r[j][1] = __ldg(xr + 2 * t + 1);
            }
            // Transpose into row-packed float4 elements.
            float4 v[8];
            v[0] = make_float4(r[0][0].x, r[1][0].x, r[2][0].x, r[3][0].x);
            v[1] = make_float4(r[0][0].y, r[1][0].y, r[2][0].y, r[3][0].y);
            v[2] = make_float4(r[0][0].z, r[1][0].z, r[2][0].z, r[3][0].z);
            v[3] = make_float4(r[0][0].w, r[1][0].w, r[2][0].w, r[3][0].w);
            v[4] = make_float4(r[0][1].x, r[1][1].x, r[2][1].x, r[3][1].x);
            v[5] = make_float4(r[0][1].y, r[1][1].y, r[2][1].y, r[3][1].y);
            v[6] = make_float4(r[0][1].z, r[1][1].z, r[2][1].z, r[3][1].z);
            v[7] = make_float4(r[0][1].w, r[1][1].w, r[2][1].w, r[3][1].w);

            substages(v, twr);

            float4* B = buf + q * kN;
            #pragma unroll
            for (int m = 0; m < 8; ++m) B[off[m]] = v[m];
        }
    }
    __syncthreads();

    // ------------- Phases 1,2: stages 3..8 (strides 8..256), smem ---------
    #pragma unroll
    for (int ph = 1; ph <= 2; ++ph) {
        const int ls = 3 * ph;          // 3 or 6
        const int s  = 1 << ls;         // 8 or 64
        const int b  = t >> ls;
        const int c  = t & (s - 1);

        float4 twr[3][4];
        #pragma unroll
        for (int u = 0; u < 3; ++u)
            #pragma unroll
            for (int pm = 0; pm < 4; ++pm)
                twr[u][pm] = tw4[(3 * ph + u) * 2048 + s * (4 * b + pm) + c];
        int off[8];
        #pragma unroll
        for (int m = 0; m < 8; ++m) off[m] = swz(b * 8 * s + c + s * m);

        // Prefetch the NEXT tile's data into L2 under phases 1-3 compute.
        if (ph == 1 && nrow0 >= 0) {
            const char* nb = reinterpret_cast<const char*>(
                x + (size_t)nrow0 * kN);
            #pragma unroll
            for (int k = 0; k < 3; ++k) {
                const int idx = t + 512 * k;
                if (idx < nchunks)
                    prefetch_l2(nb + (size_t)idx * 128);
            }
        }

        #pragma unroll
        for (int q = 0; q < NQ; ++q) {
            float4* B = buf + q * kN;
            float4 v[8];
            #pragma unroll
            for (int m = 0; m < 8; ++m) v[m] = B[off[m]];

            substages(v, twr);

            #pragma unroll
            for (int m = 0; m < 8; ++m) B[off[m]] = v[m];
        }
        __syncthreads();
    }

    // ------------- Phase 3: stages 9..11 (strides 512..2048) -> out -------
    {
        const int s = 512;  // b = 0, c = t
        float4 twr[3][4];
        #pragma unroll
        for (int u = 0; u < 3; ++u)
            #pragma unroll
            for (int pm = 0; pm < 4; ++pm)
                twr[u][pm] = tw4[(9 + u) * 2048 + s * pm + t];
        int off[8];
        #pragma unroll
        for (int m = 0; m < 8; ++m) off[m] = swz(t + s * m);

        #pragma unroll
        for (int q = 0; q < NQ; ++q) {
            float4* B = buf + q * kN;
            float4 v[8];
            #pragma unroll
            for (int m = 0; m < 8; ++m) v[m] = B[off[m]];

            substages(v, twr);

            float* o0 = out + (size_t)(row0 + 4 * q) * kN;
            float* o1 = o0 + kN;
            float* o2 = o1 + kN;
            float* o3 = o2 + kN;
            #pragma unroll
            for (int m = 0; m < 8; ++m) {
                o0[t + s * m] = v[m].x;   // warp-contiguous 4B stores
                o1[t + s * m] = v[m].y;
                o2[t + s * m] = v[m].z;
                o3[t + s * m] = v[m].w;
            }
        }
    }
    __syncthreads();   // slots reused by next tile's phase 0
}

__global__ void __launch_bounds__(kThreads, 1)
butterfly_kernel(const float* __restrict__ x,
                 const float* __restrict__ tw,
                 float* __restrict__ out) {
    extern __shared__ float4 buf[];

    for (int tile = blockIdx.x; tile < kTiles; tile += kGrid) {
        const int row0  = tile_row0(tile);
        const int nt    = tile + kGrid;
        const int nrow0 = (nt < kTiles) ? tile_row0(nt) : -1;
        const int nchk  = (nt < kTiles) ? tile_rows(nt) * (kN * 4 / 128) : 0;

        if (tile < kTiles12) {
            bf_body<3>(x, tw, out, row0, nrow0, nchk, buf);   // 12-row tile
        } else {
            bf_body<2>(x, tw, out, row0, nrow0, nchk, buf);   // 8-row tile
        }
    }
}

extern "C" void kernel_launch(void* const* d_in, const int* in_sizes, int n_in,
                              void* d_out, int out_size) {
    const float* x  = (const float*)d_in[0];   // (8192, 4096) fp32
    const float* tw = (const float*)d_in[1];   // (1,1,12,2048,2,2) fp32
    float* out      = (float*)d_out;           // (8192, 4096) fp32

    cudaFuncSetAttribute(butterfly_kernel,
                         cudaFuncAttributeMaxDynamicSharedMemorySize, kSmem);
    butterfly_kernel<<<kGrid, kThreads, kSmem>>>(x, tw, out);
}